// round 14
// baseline (speedup 1.0000x reference)
#include <cuda_runtime.h>
#include <cuda_fp16.h>

// ---------------------------------------------------------------------------
// TAGConv L3 (fp16 + HMMA) — R13 green base + ONE change:
// spmm128h uses half-warp-per-edge (16 lanes x uint4 = 256B row), 2 edges
// per iteration, unrolled x2, shfl reduction. Everything else identical.
// ---------------------------------------------------------------------------

static const int NV = 100000;
static const int NE = 3200000;
static const int NB_SCAN = 98;            // ceil(NV/1024)

// ------------------------------- scratch -----------------------------------
__device__ __align__(16) float g_dis[NV];
__device__ int   g_cnt[NV];
__device__ int   g_rowptr[NV + 1];
__device__ int   g_bsum[128];
__device__ int   g_is64;
__device__ __align__(16) int2   g_edge[NE];               // (src, f32 bits of norm)
__device__ __align__(16) __half g_H16[(size_t)NV * 64];   // layer0 concat (4x16)
__device__ __align__(16) __half g_Ha [(size_t)NV * 512];  // concat (4x128)
__device__ __align__(16) __half g_Hb [(size_t)NV * 512];
__device__ __align__(16) __half g_Wh [512 * 128];         // converted weights
__device__ __align__(16) float  g_Y  [(size_t)NV * 16];   // layer3 y_k
__device__ __align__(16) float  g_t1 [(size_t)NV * 4];
__device__ __align__(16) float  g_t2 [(size_t)NV * 4];

// ------------------------------- setup -------------------------------------
__global__ void k_init() {
    int i = blockIdx.x * blockDim.x + threadIdx.x;
    if (i < NV) { g_dis[i] = 0.0f; g_cnt[i] = 0; }
}

__global__ void k_detect(const int* __restrict__ ei32) {
    __shared__ int bad;
    if (threadIdx.x == 0) bad = 0;
    __syncthreads();
    if (ei32[2 * threadIdx.x + 1] != 0) bad = 1;
    __syncthreads();
    if (threadIdx.x == 0) g_is64 = bad ? 0 : 1;
}

__global__ void k_degcnt(const int* __restrict__ ei32,
                         const long long* __restrict__ ei64,
                         const float* __restrict__ ew) {
    int e = blockIdx.x * blockDim.x + threadIdx.x;
    if (e >= NE) return;
    int d = g_is64 ? (int)ei64[(size_t)NE + e] : ei32[(size_t)NE + e];
    atomicAdd(&g_dis[d], ew[e]);
    atomicAdd(&g_cnt[d], 1);
}

__global__ void k_rsqrt() {
    int i = blockIdx.x * blockDim.x + threadIdx.x;
    if (i >= NV) return;
    float d = g_dis[i];
    g_dis[i] = (d > 0.0f) ? rsqrtf(d) : 0.0f;
}

__global__ void k_scan1() {
    __shared__ int sh[1024];
    int tid = threadIdx.x;
    int i = blockIdx.x * 1024 + tid;
    int v = (i < NV) ? g_cnt[i] : 0;
    sh[tid] = v; __syncthreads();
    for (int off = 1; off < 1024; off <<= 1) {
        int t = (tid >= off) ? sh[tid - off] : 0;
        __syncthreads();
        sh[tid] += t;
        __syncthreads();
    }
    if (i < NV) g_rowptr[i] = sh[tid];
    if (tid == 1023) g_bsum[blockIdx.x] = sh[1023];
}

__global__ void k_scan2() {
    __shared__ int sh[128];
    int tid = threadIdx.x;
    int v = (tid < NB_SCAN) ? g_bsum[tid] : 0;
    sh[tid] = v; __syncthreads();
    for (int off = 1; off < 128; off <<= 1) {
        int t = (tid >= off) ? sh[tid - off] : 0;
        __syncthreads();
        sh[tid] += t;
        __syncthreads();
    }
    if (tid < NB_SCAN) g_bsum[tid] = sh[tid] - v;
}

__global__ void k_scan3() {
    int i = blockIdx.x * blockDim.x + threadIdx.x;
    if (i < NV) {
        int incl = g_rowptr[i];
        int c    = g_cnt[i];
        int ex   = incl - c + g_bsum[i >> 10];
        g_rowptr[i] = ex;
        g_cnt[i]    = ex;
    } else if (i == NV) {
        g_rowptr[NV] = NE;
    }
}

__global__ void k_scatter(const int* __restrict__ ei32,
                          const long long* __restrict__ ei64,
                          const float* __restrict__ ew) {
    int e = blockIdx.x * blockDim.x + threadIdx.x;
    if (e >= NE) return;
    int s, d;
    if (g_is64) { s = (int)ei64[e]; d = (int)ei64[(size_t)NE + e]; }
    else        { s = ei32[e];      d = ei32[(size_t)NE + e]; }
    int pos = atomicAdd(&g_cnt[d], 1);
    g_edge[pos] = make_int2(s, __float_as_int(g_dis[s] * ew[e] * g_dis[d]));
}

// x (NV x 16 fp32) -> fp16 into chunk0 of g_H16 (stride 64 halves)
__global__ void k_copyx(const float* __restrict__ x) {
    int t = blockIdx.x * blockDim.x + threadIdx.x;   // NV*4 float4s
    if (t >= NV * 4) return;
    int n = t >> 2, c = t & 3;
    float4 v = ((const float4*)x)[t];
    __half2 h0 = __floats2half2_rn(v.x, v.y);
    __half2 h1 = __floats2half2_rn(v.z, v.w);
    uint2 out;
    out.x = *(unsigned*)&h0; out.y = *(unsigned*)&h1;
    *(uint2*)(g_H16 + (size_t)n * 64 + c * 4) = out;
}

__global__ void k_cvtW(const float* __restrict__ W, int n) {
    int i = blockIdx.x * blockDim.x + threadIdx.x;
    if (i < n) g_Wh[i] = __float2half_rn(W[i]);
}

// ------------------------------- SpMM --------------------------------------
// width 16 fp16: 2 lanes per node, each lane one uint4 (8 halves)
__global__ void spmm16h(int k) {
    int t = blockIdx.x * blockDim.x + threadIdx.x;
    int node = t >> 1, sub = t & 1;
    if (node >= NV) return;
    const __half* in  = g_H16 + (size_t)(k - 1) * 16 + sub * 8;
    __half*       out = g_H16 + (size_t)k * 16 + sub * 8;
    int beg = g_rowptr[node], end = g_rowptr[node + 1];
    float acc[8];
#pragma unroll
    for (int i = 0; i < 8; i++) acc[i] = 0.f;
    for (int e = beg; e < end; e++) {
        int2 ed = g_edge[e];
        int s = ed.x; float w = __int_as_float(ed.y);
        uint4 raw = *(const uint4*)(in + (size_t)s * 64);
        __half2 h[4];
        *(uint4*)h = raw;
#pragma unroll
        for (int i = 0; i < 4; i++) {
            float2 f = __half22float2(h[i]);
            acc[2 * i]     = fmaf(w, f.x, acc[2 * i]);
            acc[2 * i + 1] = fmaf(w, f.y, acc[2 * i + 1]);
        }
    }
    __half2 o[4];
#pragma unroll
    for (int i = 0; i < 4; i++) o[i] = __floats2half2_rn(acc[2 * i], acc[2 * i + 1]);
    *(uint4*)(out + (size_t)node * 64) = *(uint4*)o;
}

// width 128 fp16: one warp per node, HALF-WARP PER EDGE.
// 16 lanes x uint4 (8 halves) cover the 256B row; 2 edges per iteration,
// unrolled x2 (4 edges in flight); shfl_xor(16) reduction at the end.
__global__ void spmm128h(int buf, int k) {
    int gt   = blockIdx.x * blockDim.x + threadIdx.x;
    int node = gt >> 5;
    if (node >= NV) return;
    int lane = threadIdx.x & 31;
    int half = lane >> 4, sub = lane & 15;
    __half* base = buf ? g_Hb : g_Ha;
    const __half* in  = base + (size_t)(k - 1) * 128 + sub * 8;
    __half*       out = base + (size_t)k * 128 + sub * 8;
    int beg = g_rowptr[node], end = g_rowptr[node + 1];
    float a0 = 0.f, a1 = 0.f, a2 = 0.f, a3 = 0.f;
    float a4 = 0.f, a5 = 0.f, a6 = 0.f, a7 = 0.f;

    int deg = end - beg;
    int n4  = deg & ~3;
    int eb  = beg;
    for (; eb < beg + n4; eb += 4) {
        int2 ed0 = g_edge[eb + half];
        int2 ed1 = g_edge[eb + 2 + half];
        uint4 r0 = *(const uint4*)(in + (size_t)ed0.x * 512);
        uint4 r1 = *(const uint4*)(in + (size_t)ed1.x * 512);
        float w0 = __int_as_float(ed0.y), w1 = __int_as_float(ed1.y);
        float2 f0 = __half22float2(*(__half2*)&r0.x);
        float2 f1 = __half22float2(*(__half2*)&r0.y);
        float2 f2 = __half22float2(*(__half2*)&r0.z);
        float2 f3 = __half22float2(*(__half2*)&r0.w);
        a0 = fmaf(w0, f0.x, a0); a1 = fmaf(w0, f0.y, a1);
        a2 = fmaf(w0, f1.x, a2); a3 = fmaf(w0, f1.y, a3);
        a4 = fmaf(w0, f2.x, a4); a5 = fmaf(w0, f2.y, a5);
        a6 = fmaf(w0, f3.x, a6); a7 = fmaf(w0, f3.y, a7);
        f0 = __half22float2(*(__half2*)&r1.x);
        f1 = __half22float2(*(__half2*)&r1.y);
        f2 = __half22float2(*(__half2*)&r1.z);
        f3 = __half22float2(*(__half2*)&r1.w);
        a0 = fmaf(w1, f0.x, a0); a1 = fmaf(w1, f0.y, a1);
        a2 = fmaf(w1, f1.x, a2); a3 = fmaf(w1, f1.y, a3);
        a4 = fmaf(w1, f2.x, a4); a5 = fmaf(w1, f2.y, a5);
        a6 = fmaf(w1, f3.x, a6); a7 = fmaf(w1, f3.y, a7);
    }
    for (; eb < end; eb += 2) {
        int e = eb + half;
        if (e < end) {
            int2 ed = g_edge[e];
            uint4 r = *(const uint4*)(in + (size_t)ed.x * 512);
            float w = __int_as_float(ed.y);
            float2 f0 = __half22float2(*(__half2*)&r.x);
            float2 f1 = __half22float2(*(__half2*)&r.y);
            float2 f2 = __half22float2(*(__half2*)&r.z);
            float2 f3 = __half22float2(*(__half2*)&r.w);
            a0 = fmaf(w, f0.x, a0); a1 = fmaf(w, f0.y, a1);
            a2 = fmaf(w, f1.x, a2); a3 = fmaf(w, f1.y, a3);
            a4 = fmaf(w, f2.x, a4); a5 = fmaf(w, f2.y, a5);
            a6 = fmaf(w, f3.x, a6); a7 = fmaf(w, f3.y, a7);
        }
    }
    a0 += __shfl_xor_sync(0xffffffffu, a0, 16);
    a1 += __shfl_xor_sync(0xffffffffu, a1, 16);
    a2 += __shfl_xor_sync(0xffffffffu, a2, 16);
    a3 += __shfl_xor_sync(0xffffffffu, a3, 16);
    a4 += __shfl_xor_sync(0xffffffffu, a4, 16);
    a5 += __shfl_xor_sync(0xffffffffu, a5, 16);
    a6 += __shfl_xor_sync(0xffffffffu, a6, 16);
    a7 += __shfl_xor_sync(0xffffffffu, a7, 16);
    if (half == 0) {
        __half2 o0 = __floats2half2_rn(a0, a1);
        __half2 o1 = __floats2half2_rn(a2, a3);
        __half2 o2 = __floats2half2_rn(a4, a5);
        __half2 o3 = __floats2half2_rn(a6, a7);
        uint4 ov;
        ov.x = *(unsigned*)&o0; ov.y = *(unsigned*)&o1;
        ov.z = *(unsigned*)&o2; ov.w = *(unsigned*)&o3;
        *(uint4*)(out + (size_t)node * 512) = ov;
    }
}

// width 4 Horner step (fp32): out = A*in + add (+bias on last step)
__global__ void spmm4(int step, const float* __restrict__ b3,
                      float4* __restrict__ dout) {
    int n = blockIdx.x * blockDim.x + threadIdx.x;
    if (n >= NV) return;
    const float4* Y4 = (const float4*)g_Y;
    const float4* in;  int si;
    const float4* add; int sa;
    float4* out;
    if (step == 1)      { in = Y4 + 3; si = 4; add = Y4 + 2; sa = 4; out = (float4*)g_t1; }
    else if (step == 2) { in = (const float4*)g_t1; si = 1; add = Y4 + 1; sa = 4; out = (float4*)g_t2; }
    else                { in = (const float4*)g_t2; si = 1; add = Y4;     sa = 4; out = dout; }
    float4 acc = add[(size_t)n * sa];
    if (step == 3) {
        float4 bv = *(const float4*)b3;
        acc.x += bv.x; acc.y += bv.y; acc.z += bv.z; acc.w += bv.w;
    }
    int beg = g_rowptr[n], end = g_rowptr[n + 1];
    for (int e = beg; e < end; e++) {
        int2 ed = g_edge[e];
        int s = ed.x; float w = __int_as_float(ed.y);
        float4 v = in[(size_t)s * si];
        acc.x = fmaf(w, v.x, acc.x); acc.y = fmaf(w, v.y, acc.y);
        acc.z = fmaf(w, v.z, acc.z); acc.w = fmaf(w, v.w, acc.w);
    }
    out[(size_t)n] = acc;
}

// ------------------------------- HMMA GEMM ---------------------------------
// C(NV,128) = A(NV,K fp16) @ g_Wh(K,128 fp16) + bias, optional ReLU.
// Output fp16 into chunk0 (cols 0..127) of dest buffer (stride 512 halves).
// Block: 256 thr = 8 warps (4x2), BM=128, BN=128, BK=32.
__global__ void __launch_bounds__(256) gemm_tc(int aSel, int lda, int K,
                                               int cSel,
                                               const float* __restrict__ bias,
                                               int relu) {
    __shared__ __half As[128 * 40];     // stride 40 halves (conflict-free ldmatrix)
    __shared__ __half Bs[32 * 136];     // stride 136 halves
    const __half* A = (aSel == 0) ? g_H16 : (aSel == 1) ? g_Ha : g_Hb;
    __half* C = cSel ? g_Hb : g_Ha;

    int tid = threadIdx.x;
    int lane = tid & 31, wid = tid >> 5;
    int warp_m = wid & 3;        // 0..3  -> 32 rows each
    int warp_n = wid >> 2;       // 0..1  -> 64 cols each
    int bm = blockIdx.x * 128;

    float acc[2][8][4];
#pragma unroll
    for (int i = 0; i < 2; i++)
#pragma unroll
        for (int j = 0; j < 8; j++)
#pragma unroll
            for (int l = 0; l < 4; l++) acc[i][j][l] = 0.f;

    int arow = tid >> 1;             // 0..127
    int acol = (tid & 1) * 16;       // 0 or 16 (halves)
    int brow = tid >> 3;             // 0..31
    int bcol = (tid & 7) * 16;       // halves

    for (int kt = 0; kt < K; kt += 32) {
        uint4 av0 = make_uint4(0, 0, 0, 0), av1 = make_uint4(0, 0, 0, 0);
        if (bm + arow < NV) {
            const uint4* p = (const uint4*)(A + (size_t)(bm + arow) * lda + kt + acol);
            av0 = p[0]; av1 = p[1];
        }
        *(uint4*)&As[arow * 40 + acol]     = av0;
        *(uint4*)&As[arow * 40 + acol + 8] = av1;
        const uint4* q = (const uint4*)(g_Wh + (size_t)(kt + brow) * 128 + bcol);
        *(uint4*)&Bs[brow * 136 + bcol]     = q[0];
        *(uint4*)&Bs[brow * 136 + bcol + 8] = q[1];
        __syncthreads();

#pragma unroll
        for (int ks = 0; ks < 2; ks++) {
            int k0 = ks * 16;
            unsigned af[2][4];
#pragma unroll
            for (int tm = 0; tm < 2; tm++) {
                int row = warp_m * 32 + tm * 16 + (lane & 15);
                int col = k0 + (lane >> 4) * 8;
                unsigned addr = (unsigned)__cvta_generic_to_shared(&As[row * 40 + col]);
                asm volatile(
                    "ldmatrix.sync.aligned.m8n8.x4.shared.b16 {%0,%1,%2,%3}, [%4];"
                    : "=r"(af[tm][0]), "=r"(af[tm][1]), "=r"(af[tm][2]), "=r"(af[tm][3])
                    : "r"(addr));
            }
            unsigned bf[8][2];
#pragma unroll
            for (int tp = 0; tp < 4; tp++) {
                int row = k0 + (lane & 15);
                int col = warp_n * 64 + tp * 16 + (lane >> 4) * 8;
                unsigned addr = (unsigned)__cvta_generic_to_shared(&Bs[row * 136 + col]);
                unsigned r0, r1, r2, r3;
                asm volatile(
                    "ldmatrix.sync.aligned.m8n8.x4.trans.shared.b16 {%0,%1,%2,%3}, [%4];"
                    : "=r"(r0), "=r"(r1), "=r"(r2), "=r"(r3)
                    : "r"(addr));
                bf[tp * 2][0] = r0; bf[tp * 2][1] = r1;
                bf[tp * 2 + 1][0] = r2; bf[tp * 2 + 1][1] = r3;
            }
#pragma unroll
            for (int tm = 0; tm < 2; tm++)
#pragma unroll
                for (int tn = 0; tn < 8; tn++) {
                    asm volatile(
                        "mma.sync.aligned.m16n8k16.row.col.f32.f16.f16.f32 "
                        "{%0,%1,%2,%3}, {%4,%5,%6,%7}, {%8,%9}, {%0,%1,%2,%3};"
                        : "+f"(acc[tm][tn][0]), "+f"(acc[tm][tn][1]),
                          "+f"(acc[tm][tn][2]), "+f"(acc[tm][tn][3])
                        : "r"(af[tm][0]), "r"(af[tm][1]), "r"(af[tm][2]), "r"(af[tm][3]),
                          "r"(bf[tn][0]), "r"(bf[tn][1]));
                }
        }
        __syncthreads();
    }

#pragma unroll
    for (int tm = 0; tm < 2; tm++) {
        int rbase = bm + warp_m * 32 + tm * 16 + (lane >> 2);
#pragma unroll
        for (int tn = 0; tn < 8; tn++) {
            int cc = warp_n * 64 + tn * 8 + (lane & 3) * 2;
            float bv0 = __ldg(bias + cc), bv1 = __ldg(bias + cc + 1);
            if (rbase < NV) {
                float v0 = acc[tm][tn][0] + bv0;
                float v1 = acc[tm][tn][1] + bv1;
                if (relu) { v0 = fmaxf(v0, 0.f); v1 = fmaxf(v1, 0.f); }
                *(__half2*)(C + (size_t)rbase * 512 + cc) = __floats2half2_rn(v0, v1);
            }
            if (rbase + 8 < NV) {
                float v2 = acc[tm][tn][2] + bv0;
                float v3 = acc[tm][tn][3] + bv1;
                if (relu) { v2 = fmaxf(v2, 0.f); v3 = fmaxf(v3, 0.f); }
                *(__half2*)(C + (size_t)(rbase + 8) * 512 + cc) = __floats2half2_rn(v2, v3);
            }
        }
    }
}

// Layer-3 GEMM: Y(NV,16 fp32) = h(NV,128 fp16 in g_Ha chunk0, lda=512) @ W3cat
// with W3cat column (k*4+j) = W3[k][:,j]  (W3 fp32, kept fp32 in smem).
__global__ void __launch_bounds__(256) gemm16h(const float* __restrict__ W3) {
    __shared__ float Bs[128 * 16];
    int tid = threadIdx.x;
    for (int idx = tid; idx < 2048; idx += 256) {
        int k = idx >> 9, rem = idx & 511, i2 = rem >> 2, j = rem & 3;
        Bs[i2 * 16 + (k << 2) + j] = W3[idx];
    }
    __syncthreads();
    int g = tid >> 4, n = tid & 15;
    int m = blockIdx.x * 16 + g;
    if (m >= NV) return;
    const __half* a = g_Ha + (size_t)m * 512;
    float acc = 0.f;
#pragma unroll 8
    for (int k = 0; k < 128; k++)
        acc = fmaf(__half2float(a[k]), Bs[k * 16 + n], acc);
    g_Y[(size_t)m * 16 + n] = acc;
}

// ------------------------------- driver ------------------------------------
extern "C" void kernel_launch(void* const* d_in, const int* in_sizes, int n_in,
                              void* d_out, int out_size) {
    const float* x  = (const float*)d_in[0];
    const void*  ei = d_in[1];
    const float* ew = (const float*)d_in[2];
    const float* W0 = (const float*)d_in[3];
    const float* b0 = (const float*)d_in[4];
    const float* W1 = (const float*)d_in[5];
    const float* b1 = (const float*)d_in[6];
    const float* W2 = (const float*)d_in[7];
    const float* b2 = (const float*)d_in[8];
    const float* W3 = (const float*)d_in[9];
    const float* b3 = (const float*)d_in[10];

    const int* ei32 = (const int*)ei;
    const long long* ei64 = (const long long*)ei;

    k_init<<<(NV + 255) / 256, 256>>>();
    k_detect<<<1, 1024>>>(ei32);
    k_degcnt<<<(NE + 255) / 256, 256>>>(ei32, ei64, ew);
    k_rsqrt<<<(NV + 255) / 256, 256>>>();
    k_scan1<<<NB_SCAN, 1024>>>();
    k_scan2<<<1, 128>>>();
    k_scan3<<<(NV + 256) / 256, 256>>>();
    k_scatter<<<(NE + 255) / 256, 256>>>(ei32, ei64, ew);
    k_copyx<<<(NV * 4 + 255) / 256, 256>>>(x);

    const int GEMM_BLOCKS = (NV + 127) / 128;

    // layer 0: propagate width 16, GEMM (NV,64)@(64,128) -> Ha chunk0, ReLU
    for (int k = 1; k <= 3; k++)
        spmm16h<<<(NV * 2 + 255) / 256, 256>>>(k);
    k_cvtW<<<(64 * 128 + 255) / 256, 256>>>(W0, 64 * 128);
    gemm_tc<<<GEMM_BLOCKS, 256>>>(0, 64, 64, 0, b0, 1);

    // layer 1: propagate width 128 in Ha, GEMM (NV,512)@(512,128) -> Hb, ReLU
    for (int k = 1; k <= 3; k++)
        spmm128h<<<(NV * 32 + 255) / 256, 256>>>(0, k);
    k_cvtW<<<(512 * 128 + 255) / 256, 256>>>(W1, 512 * 128);
    gemm_tc<<<GEMM_BLOCKS, 256>>>(1, 512, 512, 1, b1, 1);

    // layer 2: propagate width 128 in Hb, GEMM -> Ha chunk0, ReLU
    for (int k = 1; k <= 3; k++)
        spmm128h<<<(NV * 32 + 255) / 256, 256>>>(1, k);
    k_cvtW<<<(512 * 128 + 255) / 256, 256>>>(W2, 512 * 128);
    gemm_tc<<<GEMM_BLOCKS, 256>>>(2, 512, 512, 0, b2, 1);

    // layer 3: y_k = h @ W3[k]; Horner with width-4 fp32 SpMMs
    gemm16h<<<(NV + 15) / 16, 256>>>(W3);
    spmm4<<<(NV + 255) / 256, 256>>>(1, nullptr, nullptr);
    spmm4<<<(NV + 255) / 256, 256>>>(2, nullptr, nullptr);
    spmm4<<<(NV + 255) / 256, 256>>>(3, b3, (float4*)d_out);
}

// round 15
// speedup vs baseline: 1.0064x; 1.0064x over previous
#include <cuda_runtime.h>
#include <cuda_fp16.h>

// ---------------------------------------------------------------------------
// TAGConv L3 (fp16 + HMMA) — R13 green base + ONE change:
// spmm128h edge loop unrolled x4 (warp-per-node, uint2 per lane preserved).
// ---------------------------------------------------------------------------

static const int NV = 100000;
static const int NE = 3200000;
static const int NB_SCAN = 98;            // ceil(NV/1024)

// ------------------------------- scratch -----------------------------------
__device__ __align__(16) float g_dis[NV];
__device__ int   g_cnt[NV];
__device__ int   g_rowptr[NV + 1];
__device__ int   g_bsum[128];
__device__ int   g_is64;
__device__ __align__(16) int2   g_edge[NE];               // (src, f32 bits of norm)
__device__ __align__(16) __half g_H16[(size_t)NV * 64];   // layer0 concat (4x16)
__device__ __align__(16) __half g_Ha [(size_t)NV * 512];  // concat (4x128)
__device__ __align__(16) __half g_Hb [(size_t)NV * 512];
__device__ __align__(16) __half g_Wh [512 * 128];         // converted weights
__device__ __align__(16) float  g_Y  [(size_t)NV * 16];   // layer3 y_k
__device__ __align__(16) float  g_t1 [(size_t)NV * 4];
__device__ __align__(16) float  g_t2 [(size_t)NV * 4];

// ------------------------------- setup -------------------------------------
__global__ void k_init() {
    int i = blockIdx.x * blockDim.x + threadIdx.x;
    if (i < NV) { g_dis[i] = 0.0f; g_cnt[i] = 0; }
}

__global__ void k_detect(const int* __restrict__ ei32) {
    __shared__ int bad;
    if (threadIdx.x == 0) bad = 0;
    __syncthreads();
    if (ei32[2 * threadIdx.x + 1] != 0) bad = 1;
    __syncthreads();
    if (threadIdx.x == 0) g_is64 = bad ? 0 : 1;
}

__global__ void k_degcnt(const int* __restrict__ ei32,
                         const long long* __restrict__ ei64,
                         const float* __restrict__ ew) {
    int e = blockIdx.x * blockDim.x + threadIdx.x;
    if (e >= NE) return;
    int d = g_is64 ? (int)ei64[(size_t)NE + e] : ei32[(size_t)NE + e];
    atomicAdd(&g_dis[d], ew[e]);
    atomicAdd(&g_cnt[d], 1);
}

__global__ void k_rsqrt() {
    int i = blockIdx.x * blockDim.x + threadIdx.x;
    if (i >= NV) return;
    float d = g_dis[i];
    g_dis[i] = (d > 0.0f) ? rsqrtf(d) : 0.0f;
}

__global__ void k_scan1() {
    __shared__ int sh[1024];
    int tid = threadIdx.x;
    int i = blockIdx.x * 1024 + tid;
    int v = (i < NV) ? g_cnt[i] : 0;
    sh[tid] = v; __syncthreads();
    for (int off = 1; off < 1024; off <<= 1) {
        int t = (tid >= off) ? sh[tid - off] : 0;
        __syncthreads();
        sh[tid] += t;
        __syncthreads();
    }
    if (i < NV) g_rowptr[i] = sh[tid];
    if (tid == 1023) g_bsum[blockIdx.x] = sh[1023];
}

__global__ void k_scan2() {
    __shared__ int sh[128];
    int tid = threadIdx.x;
    int v = (tid < NB_SCAN) ? g_bsum[tid] : 0;
    sh[tid] = v; __syncthreads();
    for (int off = 1; off < 128; off <<= 1) {
        int t = (tid >= off) ? sh[tid - off] : 0;
        __syncthreads();
        sh[tid] += t;
        __syncthreads();
    }
    if (tid < NB_SCAN) g_bsum[tid] = sh[tid] - v;
}

__global__ void k_scan3() {
    int i = blockIdx.x * blockDim.x + threadIdx.x;
    if (i < NV) {
        int incl = g_rowptr[i];
        int c    = g_cnt[i];
        int ex   = incl - c + g_bsum[i >> 10];
        g_rowptr[i] = ex;
        g_cnt[i]    = ex;
    } else if (i == NV) {
        g_rowptr[NV] = NE;
    }
}

__global__ void k_scatter(const int* __restrict__ ei32,
                          const long long* __restrict__ ei64,
                          const float* __restrict__ ew) {
    int e = blockIdx.x * blockDim.x + threadIdx.x;
    if (e >= NE) return;
    int s, d;
    if (g_is64) { s = (int)ei64[e]; d = (int)ei64[(size_t)NE + e]; }
    else        { s = ei32[e];      d = ei32[(size_t)NE + e]; }
    int pos = atomicAdd(&g_cnt[d], 1);
    g_edge[pos] = make_int2(s, __float_as_int(g_dis[s] * ew[e] * g_dis[d]));
}

// x (NV x 16 fp32) -> fp16 into chunk0 of g_H16 (stride 64 halves)
__global__ void k_copyx(const float* __restrict__ x) {
    int t = blockIdx.x * blockDim.x + threadIdx.x;   // NV*4 float4s
    if (t >= NV * 4) return;
    int n = t >> 2, c = t & 3;
    float4 v = ((const float4*)x)[t];
    __half2 h0 = __floats2half2_rn(v.x, v.y);
    __half2 h1 = __floats2half2_rn(v.z, v.w);
    uint2 out;
    out.x = *(unsigned*)&h0; out.y = *(unsigned*)&h1;
    *(uint2*)(g_H16 + (size_t)n * 64 + c * 4) = out;
}

__global__ void k_cvtW(const float* __restrict__ W, int n) {
    int i = blockIdx.x * blockDim.x + threadIdx.x;
    if (i < n) g_Wh[i] = __float2half_rn(W[i]);
}

// ------------------------------- SpMM --------------------------------------
// width 16 fp16: 2 lanes per node, each lane one uint4 (8 halves)
__global__ void spmm16h(int k) {
    int t = blockIdx.x * blockDim.x + threadIdx.x;
    int node = t >> 1, sub = t & 1;
    if (node >= NV) return;
    const __half* in  = g_H16 + (size_t)(k - 1) * 16 + sub * 8;
    __half*       out = g_H16 + (size_t)k * 16 + sub * 8;
    int beg = g_rowptr[node], end = g_rowptr[node + 1];
    float acc[8];
#pragma unroll
    for (int i = 0; i < 8; i++) acc[i] = 0.f;
    for (int e = beg; e < end; e++) {
        int2 ed = g_edge[e];
        int s = ed.x; float w = __int_as_float(ed.y);
        uint4 raw = *(const uint4*)(in + (size_t)s * 64);
        __half2 h[4];
        *(uint4*)h = raw;
#pragma unroll
        for (int i = 0; i < 4; i++) {
            float2 f = __half22float2(h[i]);
            acc[2 * i]     = fmaf(w, f.x, acc[2 * i]);
            acc[2 * i + 1] = fmaf(w, f.y, acc[2 * i + 1]);
        }
    }
    __half2 o[4];
#pragma unroll
    for (int i = 0; i < 4; i++) o[i] = __floats2half2_rn(acc[2 * i], acc[2 * i + 1]);
    *(uint4*)(out + (size_t)node * 64) = *(uint4*)o;
}

// width 128 fp16: one warp per node, lane owns 4 halves (uint2), unroll x4
__global__ void spmm128h(int buf, int k) {
    int gt   = blockIdx.x * blockDim.x + threadIdx.x;
    int node = gt >> 5;
    int lane = threadIdx.x & 31;
    if (node >= NV) return;
    __half* base = buf ? g_Hb : g_Ha;
    const __half* in  = base + (size_t)(k - 1) * 128 + lane * 4;
    __half*       out = base + (size_t)k * 128 + lane * 4;
    int beg = g_rowptr[node], end = g_rowptr[node + 1];
    float ax = 0.f, ay = 0.f, az = 0.f, aw = 0.f;
    int e = beg;
    int n4 = (end - beg) & ~3;
    for (; e < beg + n4; e += 4) {
        int2 ed0 = g_edge[e];
        int2 ed1 = g_edge[e + 1];
        int2 ed2 = g_edge[e + 2];
        int2 ed3 = g_edge[e + 3];
        uint2 r0 = *(const uint2*)(in + (size_t)ed0.x * 512);
        uint2 r1 = *(const uint2*)(in + (size_t)ed1.x * 512);
        uint2 r2 = *(const uint2*)(in + (size_t)ed2.x * 512);
        uint2 r3 = *(const uint2*)(in + (size_t)ed3.x * 512);
        float w0 = __int_as_float(ed0.y), w1 = __int_as_float(ed1.y);
        float w2 = __int_as_float(ed2.y), w3 = __int_as_float(ed3.y);
        float2 f0 = __half22float2(*(__half2*)&r0.x);
        float2 f1 = __half22float2(*(__half2*)&r0.y);
        ax = fmaf(w0, f0.x, ax); ay = fmaf(w0, f0.y, ay);
        az = fmaf(w0, f1.x, az); aw = fmaf(w0, f1.y, aw);
        f0 = __half22float2(*(__half2*)&r1.x);
        f1 = __half22float2(*(__half2*)&r1.y);
        ax = fmaf(w1, f0.x, ax); ay = fmaf(w1, f0.y, ay);
        az = fmaf(w1, f1.x, az); aw = fmaf(w1, f1.y, aw);
        f0 = __half22float2(*(__half2*)&r2.x);
        f1 = __half22float2(*(__half2*)&r2.y);
        ax = fmaf(w2, f0.x, ax); ay = fmaf(w2, f0.y, ay);
        az = fmaf(w2, f1.x, az); aw = fmaf(w2, f1.y, aw);
        f0 = __half22float2(*(__half2*)&r3.x);
        f1 = __half22float2(*(__half2*)&r3.y);
        ax = fmaf(w3, f0.x, ax); ay = fmaf(w3, f0.y, ay);
        az = fmaf(w3, f1.x, az); aw = fmaf(w3, f1.y, aw);
    }
    for (; e < end; e++) {
        int2 ed = g_edge[e];
        int s = ed.x; float w = __int_as_float(ed.y);
        uint2 r0 = *(const uint2*)(in + (size_t)s * 512);
        float2 f0 = __half22float2(*(__half2*)&r0.x);
        float2 f1 = __half22float2(*(__half2*)&r0.y);
        ax = fmaf(w, f0.x, ax); ay = fmaf(w, f0.y, ay);
        az = fmaf(w, f1.x, az); aw = fmaf(w, f1.y, aw);
    }
    __half2 o0 = __floats2half2_rn(ax, ay);
    __half2 o1 = __floats2half2_rn(az, aw);
    uint2 o; o.x = *(unsigned*)&o0; o.y = *(unsigned*)&o1;
    *(uint2*)(out + (size_t)node * 512) = o;
}

// width 4 Horner step (fp32): out = A*in + add (+bias on last step)
__global__ void spmm4(int step, const float* __restrict__ b3,
                      float4* __restrict__ dout) {
    int n = blockIdx.x * blockDim.x + threadIdx.x;
    if (n >= NV) return;
    const float4* Y4 = (const float4*)g_Y;
    const float4* in;  int si;
    const float4* add; int sa;
    float4* out;
    if (step == 1)      { in = Y4 + 3; si = 4; add = Y4 + 2; sa = 4; out = (float4*)g_t1; }
    else if (step == 2) { in = (const float4*)g_t1; si = 1; add = Y4 + 1; sa = 4; out = (float4*)g_t2; }
    else                { in = (const float4*)g_t2; si = 1; add = Y4;     sa = 4; out = dout; }
    float4 acc = add[(size_t)n * sa];
    if (step == 3) {
        float4 bv = *(const float4*)b3;
        acc.x += bv.x; acc.y += bv.y; acc.z += bv.z; acc.w += bv.w;
    }
    int beg = g_rowptr[n], end = g_rowptr[n + 1];
    for (int e = beg; e < end; e++) {
        int2 ed = g_edge[e];
        int s = ed.x; float w = __int_as_float(ed.y);
        float4 v = in[(size_t)s * si];
        acc.x = fmaf(w, v.x, acc.x); acc.y = fmaf(w, v.y, acc.y);
        acc.z = fmaf(w, v.z, acc.z); acc.w = fmaf(w, v.w, acc.w);
    }
    out[(size_t)n] = acc;
}

// ------------------------------- HMMA GEMM ---------------------------------
// C(NV,128) = A(NV,K fp16) @ g_Wh(K,128 fp16) + bias, optional ReLU.
// Output fp16 into chunk0 (cols 0..127) of dest buffer (stride 512 halves).
// Block: 256 thr = 8 warps (4x2), BM=128, BN=128, BK=32.
__global__ void __launch_bounds__(256) gemm_tc(int aSel, int lda, int K,
                                               int cSel,
                                               const float* __restrict__ bias,
                                               int relu) {
    __shared__ __half As[128 * 40];     // stride 40 halves (conflict-free ldmatrix)
    __shared__ __half Bs[32 * 136];     // stride 136 halves
    const __half* A = (aSel == 0) ? g_H16 : (aSel == 1) ? g_Ha : g_Hb;
    __half* C = cSel ? g_Hb : g_Ha;

    int tid = threadIdx.x;
    int lane = tid & 31, wid = tid >> 5;
    int warp_m = wid & 3;        // 0..3  -> 32 rows each
    int warp_n = wid >> 2;       // 0..1  -> 64 cols each
    int bm = blockIdx.x * 128;

    float acc[2][8][4];
#pragma unroll
    for (int i = 0; i < 2; i++)
#pragma unroll
        for (int j = 0; j < 8; j++)
#pragma unroll
            for (int l = 0; l < 4; l++) acc[i][j][l] = 0.f;

    int arow = tid >> 1;             // 0..127
    int acol = (tid & 1) * 16;       // 0 or 16 (halves)
    int brow = tid >> 3;             // 0..31
    int bcol = (tid & 7) * 16;       // halves

    for (int kt = 0; kt < K; kt += 32) {
        uint4 av0 = make_uint4(0, 0, 0, 0), av1 = make_uint4(0, 0, 0, 0);
        if (bm + arow < NV) {
            const uint4* p = (const uint4*)(A + (size_t)(bm + arow) * lda + kt + acol);
            av0 = p[0]; av1 = p[1];
        }
        *(uint4*)&As[arow * 40 + acol]     = av0;
        *(uint4*)&As[arow * 40 + acol + 8] = av1;
        const uint4* q = (const uint4*)(g_Wh + (size_t)(kt + brow) * 128 + bcol);
        *(uint4*)&Bs[brow * 136 + bcol]     = q[0];
        *(uint4*)&Bs[brow * 136 + bcol + 8] = q[1];
        __syncthreads();

#pragma unroll
        for (int ks = 0; ks < 2; ks++) {
            int k0 = ks * 16;
            unsigned af[2][4];
#pragma unroll
            for (int tm = 0; tm < 2; tm++) {
                int row = warp_m * 32 + tm * 16 + (lane & 15);
                int col = k0 + (lane >> 4) * 8;
                unsigned addr = (unsigned)__cvta_generic_to_shared(&As[row * 40 + col]);
                asm volatile(
                    "ldmatrix.sync.aligned.m8n8.x4.shared.b16 {%0,%1,%2,%3}, [%4];"
                    : "=r"(af[tm][0]), "=r"(af[tm][1]), "=r"(af[tm][2]), "=r"(af[tm][3])
                    : "r"(addr));
            }
            unsigned bf[8][2];
#pragma unroll
            for (int tp = 0; tp < 4; tp++) {
                int row = k0 + (lane & 15);
                int col = warp_n * 64 + tp * 16 + (lane >> 4) * 8;
                unsigned addr = (unsigned)__cvta_generic_to_shared(&Bs[row * 136 + col]);
                unsigned r0, r1, r2, r3;
                asm volatile(
                    "ldmatrix.sync.aligned.m8n8.x4.trans.shared.b16 {%0,%1,%2,%3}, [%4];"
                    : "=r"(r0), "=r"(r1), "=r"(r2), "=r"(r3)
                    : "r"(addr));
                bf[tp * 2][0] = r0; bf[tp * 2][1] = r1;
                bf[tp * 2 + 1][0] = r2; bf[tp * 2 + 1][1] = r3;
            }
#pragma unroll
            for (int tm = 0; tm < 2; tm++)
#pragma unroll
                for (int tn = 0; tn < 8; tn++) {
                    asm volatile(
                        "mma.sync.aligned.m16n8k16.row.col.f32.f16.f16.f32 "
                        "{%0,%1,%2,%3}, {%4,%5,%6,%7}, {%8,%9}, {%0,%1,%2,%3};"
                        : "+f"(acc[tm][tn][0]), "+f"(acc[tm][tn][1]),
                          "+f"(acc[tm][tn][2]), "+f"(acc[tm][tn][3])
                        : "r"(af[tm][0]), "r"(af[tm][1]), "r"(af[tm][2]), "r"(af[tm][3]),
                          "r"(bf[tn][0]), "r"(bf[tn][1]));
                }
        }
        __syncthreads();
    }

#pragma unroll
    for (int tm = 0; tm < 2; tm++) {
        int rbase = bm + warp_m * 32 + tm * 16 + (lane >> 2);
#pragma unroll
        for (int tn = 0; tn < 8; tn++) {
            int cc = warp_n * 64 + tn * 8 + (lane & 3) * 2;
            float bv0 = __ldg(bias + cc), bv1 = __ldg(bias + cc + 1);
            if (rbase < NV) {
                float v0 = acc[tm][tn][0] + bv0;
                float v1 = acc[tm][tn][1] + bv1;
                if (relu) { v0 = fmaxf(v0, 0.f); v1 = fmaxf(v1, 0.f); }
                *(__half2*)(C + (size_t)rbase * 512 + cc) = __floats2half2_rn(v0, v1);
            }
            if (rbase + 8 < NV) {
                float v2 = acc[tm][tn][2] + bv0;
                float v3 = acc[tm][tn][3] + bv1;
                if (relu) { v2 = fmaxf(v2, 0.f); v3 = fmaxf(v3, 0.f); }
                *(__half2*)(C + (size_t)(rbase + 8) * 512 + cc) = __floats2half2_rn(v2, v3);
            }
        }
    }
}

// Layer-3 GEMM: Y(NV,16 fp32) = h(NV,128 fp16 in g_Ha chunk0, lda=512) @ W3cat
// with W3cat column (k*4+j) = W3[k][:,j]  (W3 fp32, kept fp32 in smem).
__global__ void __launch_bounds__(256) gemm16h(const float* __restrict__ W3) {
    __shared__ float Bs[128 * 16];
    int tid = threadIdx.x;
    for (int idx = tid; idx < 2048; idx += 256) {
        int k = idx >> 9, rem = idx & 511, i2 = rem >> 2, j = rem & 3;
        Bs[i2 * 16 + (k << 2) + j] = W3[idx];
    }
    __syncthreads();
    int g = tid >> 4, n = tid & 15;
    int m = blockIdx.x * 16 + g;
    if (m >= NV) return;
    const __half* a = g_Ha + (size_t)m * 512;
    float acc = 0.f;
#pragma unroll 8
    for (int k = 0; k < 128; k++)
        acc = fmaf(__half2float(a[k]), Bs[k * 16 + n], acc);
    g_Y[(size_t)m * 16 + n] = acc;
}

// ------------------------------- driver ------------------------------------
extern "C" void kernel_launch(void* const* d_in, const int* in_sizes, int n_in,
                              void* d_out, int out_size) {
    const float* x  = (const float*)d_in[0];
    const void*  ei = d_in[1];
    const float* ew = (const float*)d_in[2];
    const float* W0 = (const float*)d_in[3];
    const float* b0 = (const float*)d_in[4];
    const float* W1 = (const float*)d_in[5];
    const float* b1 = (const float*)d_in[6];
    const float* W2 = (const float*)d_in[7];
    const float* b2 = (const float*)d_in[8];
    const float* W3 = (const float*)d_in[9];
    const float* b3 = (const float*)d_in[10];

    const int* ei32 = (const int*)ei;
    const long long* ei64 = (const long long*)ei;

    k_init<<<(NV + 255) / 256, 256>>>();
    k_detect<<<1, 1024>>>(ei32);
    k_degcnt<<<(NE + 255) / 256, 256>>>(ei32, ei64, ew);
    k_rsqrt<<<(NV + 255) / 256, 256>>>();
    k_scan1<<<NB_SCAN, 1024>>>();
    k_scan2<<<1, 128>>>();
    k_scan3<<<(NV + 256) / 256, 256>>>();
    k_scatter<<<(NE + 255) / 256, 256>>>(ei32, ei64, ew);
    k_copyx<<<(NV * 4 + 255) / 256, 256>>>(x);

    const int GEMM_BLOCKS = (NV + 127) / 128;

    // layer 0: propagate width 16, GEMM (NV,64)@(64,128) -> Ha chunk0, ReLU
    for (int k = 1; k <= 3; k++)
        spmm16h<<<(NV * 2 + 255) / 256, 256>>>(k);
    k_cvtW<<<(64 * 128 + 255) / 256, 256>>>(W0, 64 * 128);
    gemm_tc<<<GEMM_BLOCKS, 256>>>(0, 64, 64, 0, b0, 1);

    // layer 1: propagate width 128 in Ha, GEMM (NV,512)@(512,128) -> Hb, ReLU
    for (int k = 1; k <= 3; k++)
        spmm128h<<<(NV * 32 + 255) / 256, 256>>>(0, k);
    k_cvtW<<<(512 * 128 + 255) / 256, 256>>>(W1, 512 * 128);
    gemm_tc<<<GEMM_BLOCKS, 256>>>(1, 512, 512, 1, b1, 1);

    // layer 2: propagate width 128 in Hb, GEMM -> Ha chunk0, ReLU
    for (int k = 1; k <= 3; k++)
        spmm128h<<<(NV * 32 + 255) / 256, 256>>>(1, k);
    k_cvtW<<<(512 * 128 + 255) / 256, 256>>>(W2, 512 * 128);
    gemm_tc<<<GEMM_BLOCKS, 256>>>(2, 512, 512, 0, b2, 1);

    // layer 3: y_k = h @ W3[k]; Horner with width-4 fp32 SpMMs
    gemm16h<<<(NV + 15) / 16, 256>>>(W3);
    spmm4<<<(NV + 255) / 256, 256>>>(1, nullptr, nullptr);
    spmm4<<<(NV + 255) / 256, 256>>>(2, nullptr, nullptr);
    spmm4<<<(NV + 255) / 256, 256>>>(3, b3, (float4*)d_out);
}

// round 17
// speedup vs baseline: 1.0800x; 1.0731x over previous
#include <cuda_runtime.h>
#include <cuda_fp16.h>

// ---------------------------------------------------------------------------
// TAGConv L3 (fp16 + HMMA) — R13 green base + ONE change:
// gemm_tc 2-stage cp.async double-buffered pipeline (offsets FIXED: second
// fragment is +16 bytes dst / +8 halves src, matching the R2 layout).
// ---------------------------------------------------------------------------

static const int NV = 100000;
static const int NE = 3200000;
static const int NB_SCAN = 98;            // ceil(NV/1024)

// ------------------------------- scratch -----------------------------------
__device__ __align__(16) float g_dis[NV];
__device__ int   g_cnt[NV];
__device__ int   g_rowptr[NV + 1];
__device__ int   g_bsum[128];
__device__ int   g_is64;
__device__ __align__(16) int2   g_edge[NE];               // (src, f32 bits of norm)
__device__ __align__(16) __half g_H16[(size_t)NV * 64];   // layer0 concat (4x16)
__device__ __align__(16) __half g_Ha [(size_t)NV * 512];  // concat (4x128)
__device__ __align__(16) __half g_Hb [(size_t)NV * 512];
__device__ __align__(16) __half g_Wh [512 * 128];         // converted weights
__device__ __align__(16) float  g_Y  [(size_t)NV * 16];   // layer3 y_k
__device__ __align__(16) float  g_t1 [(size_t)NV * 4];
__device__ __align__(16) float  g_t2 [(size_t)NV * 4];

// ------------------------------- setup -------------------------------------
__global__ void k_init() {
    int i = blockIdx.x * blockDim.x + threadIdx.x;
    if (i < NV) { g_dis[i] = 0.0f; g_cnt[i] = 0; }
}

__global__ void k_detect(const int* __restrict__ ei32) {
    __shared__ int bad;
    if (threadIdx.x == 0) bad = 0;
    __syncthreads();
    if (ei32[2 * threadIdx.x + 1] != 0) bad = 1;
    __syncthreads();
    if (threadIdx.x == 0) g_is64 = bad ? 0 : 1;
}

__global__ void k_degcnt(const int* __restrict__ ei32,
                         const long long* __restrict__ ei64,
                         const float* __restrict__ ew) {
    int e = blockIdx.x * blockDim.x + threadIdx.x;
    if (e >= NE) return;
    int d = g_is64 ? (int)ei64[(size_t)NE + e] : ei32[(size_t)NE + e];
    atomicAdd(&g_dis[d], ew[e]);
    atomicAdd(&g_cnt[d], 1);
}

__global__ void k_rsqrt() {
    int i = blockIdx.x * blockDim.x + threadIdx.x;
    if (i >= NV) return;
    float d = g_dis[i];
    g_dis[i] = (d > 0.0f) ? rsqrtf(d) : 0.0f;
}

__global__ void k_scan1() {
    __shared__ int sh[1024];
    int tid = threadIdx.x;
    int i = blockIdx.x * 1024 + tid;
    int v = (i < NV) ? g_cnt[i] : 0;
    sh[tid] = v; __syncthreads();
    for (int off = 1; off < 1024; off <<= 1) {
        int t = (tid >= off) ? sh[tid - off] : 0;
        __syncthreads();
        sh[tid] += t;
        __syncthreads();
    }
    if (i < NV) g_rowptr[i] = sh[tid];
    if (tid == 1023) g_bsum[blockIdx.x] = sh[1023];
}

__global__ void k_scan2() {
    __shared__ int sh[128];
    int tid = threadIdx.x;
    int v = (tid < NB_SCAN) ? g_bsum[tid] : 0;
    sh[tid] = v; __syncthreads();
    for (int off = 1; off < 128; off <<= 1) {
        int t = (tid >= off) ? sh[tid - off] : 0;
        __syncthreads();
        sh[tid] += t;
        __syncthreads();
    }
    if (tid < NB_SCAN) g_bsum[tid] = sh[tid] - v;
}

__global__ void k_scan3() {
    int i = blockIdx.x * blockDim.x + threadIdx.x;
    if (i < NV) {
        int incl = g_rowptr[i];
        int c    = g_cnt[i];
        int ex   = incl - c + g_bsum[i >> 10];
        g_rowptr[i] = ex;
        g_cnt[i]    = ex;
    } else if (i == NV) {
        g_rowptr[NV] = NE;
    }
}

__global__ void k_scatter(const int* __restrict__ ei32,
                          const long long* __restrict__ ei64,
                          const float* __restrict__ ew) {
    int e = blockIdx.x * blockDim.x + threadIdx.x;
    if (e >= NE) return;
    int s, d;
    if (g_is64) { s = (int)ei64[e]; d = (int)ei64[(size_t)NE + e]; }
    else        { s = ei32[e];      d = ei32[(size_t)NE + e]; }
    int pos = atomicAdd(&g_cnt[d], 1);
    g_edge[pos] = make_int2(s, __float_as_int(g_dis[s] * ew[e] * g_dis[d]));
}

// x (NV x 16 fp32) -> fp16 into chunk0 of g_H16 (stride 64 halves)
__global__ void k_copyx(const float* __restrict__ x) {
    int t = blockIdx.x * blockDim.x + threadIdx.x;   // NV*4 float4s
    if (t >= NV * 4) return;
    int n = t >> 2, c = t & 3;
    float4 v = ((const float4*)x)[t];
    __half2 h0 = __floats2half2_rn(v.x, v.y);
    __half2 h1 = __floats2half2_rn(v.z, v.w);
    uint2 out;
    out.x = *(unsigned*)&h0; out.y = *(unsigned*)&h1;
    *(uint2*)(g_H16 + (size_t)n * 64 + c * 4) = out;
}

__global__ void k_cvtW(const float* __restrict__ W, int n) {
    int i = blockIdx.x * blockDim.x + threadIdx.x;
    if (i < n) g_Wh[i] = __float2half_rn(W[i]);
}

// ------------------------------- SpMM --------------------------------------
// width 16 fp16: 2 lanes per node, each lane one uint4 (8 halves)
__global__ void spmm16h(int k) {
    int t = blockIdx.x * blockDim.x + threadIdx.x;
    int node = t >> 1, sub = t & 1;
    if (node >= NV) return;
    const __half* in  = g_H16 + (size_t)(k - 1) * 16 + sub * 8;
    __half*       out = g_H16 + (size_t)k * 16 + sub * 8;
    int beg = g_rowptr[node], end = g_rowptr[node + 1];
    float acc[8];
#pragma unroll
    for (int i = 0; i < 8; i++) acc[i] = 0.f;
    for (int e = beg; e < end; e++) {
        int2 ed = g_edge[e];
        int s = ed.x; float w = __int_as_float(ed.y);
        uint4 raw = *(const uint4*)(in + (size_t)s * 64);
        __half2 h[4];
        *(uint4*)h = raw;
#pragma unroll
        for (int i = 0; i < 4; i++) {
            float2 f = __half22float2(h[i]);
            acc[2 * i]     = fmaf(w, f.x, acc[2 * i]);
            acc[2 * i + 1] = fmaf(w, f.y, acc[2 * i + 1]);
        }
    }
    __half2 o[4];
#pragma unroll
    for (int i = 0; i < 4; i++) o[i] = __floats2half2_rn(acc[2 * i], acc[2 * i + 1]);
    *(uint4*)(out + (size_t)node * 64) = *(uint4*)o;
}

// width 128 fp16: one warp per node, lane owns 4 halves (uint2) — R13 body
__global__ void spmm128h(int buf, int k) {
    int gt   = blockIdx.x * blockDim.x + threadIdx.x;
    int node = gt >> 5;
    int lane = threadIdx.x & 31;
    if (node >= NV) return;
    __half* base = buf ? g_Hb : g_Ha;
    const __half* in  = base + (size_t)(k - 1) * 128 + lane * 4;
    __half*       out = base + (size_t)k * 128 + lane * 4;
    int beg = g_rowptr[node], end = g_rowptr[node + 1];
    float ax = 0.f, ay = 0.f, az = 0.f, aw = 0.f;
    int e = beg;
    for (; e + 1 < end; e += 2) {
        int2 ed0 = g_edge[e];
        int2 ed1 = g_edge[e + 1];
        int s0 = ed0.x; float w0 = __int_as_float(ed0.y);
        int s1 = ed1.x; float w1 = __int_as_float(ed1.y);
        uint2 r0 = *(const uint2*)(in + (size_t)s0 * 512);
        uint2 r1 = *(const uint2*)(in + (size_t)s1 * 512);
        float2 f0 = __half22float2(*(__half2*)&r0.x);
        float2 f1 = __half22float2(*(__half2*)&r0.y);
        float2 f2 = __half22float2(*(__half2*)&r1.x);
        float2 f3 = __half22float2(*(__half2*)&r1.y);
        ax = fmaf(w0, f0.x, ax); ay = fmaf(w0, f0.y, ay);
        az = fmaf(w0, f1.x, az); aw = fmaf(w0, f1.y, aw);
        ax = fmaf(w1, f2.x, ax); ay = fmaf(w1, f2.y, ay);
        az = fmaf(w1, f3.x, az); aw = fmaf(w1, f3.y, aw);
    }
    if (e < end) {
        int2 ed = g_edge[e];
        int s = ed.x; float w = __int_as_float(ed.y);
        uint2 r0 = *(const uint2*)(in + (size_t)s * 512);
        float2 f0 = __half22float2(*(__half2*)&r0.x);
        float2 f1 = __half22float2(*(__half2*)&r0.y);
        ax = fmaf(w, f0.x, ax); ay = fmaf(w, f0.y, ay);
        az = fmaf(w, f1.x, az); aw = fmaf(w, f1.y, aw);
    }
    __half2 o0 = __floats2half2_rn(ax, ay);
    __half2 o1 = __floats2half2_rn(az, aw);
    uint2 o; o.x = *(unsigned*)&o0; o.y = *(unsigned*)&o1;
    *(uint2*)(out + (size_t)node * 512) = o;
}

// width 4 Horner step (fp32): out = A*in + add (+bias on last step)
__global__ void spmm4(int step, const float* __restrict__ b3,
                      float4* __restrict__ dout) {
    int n = blockIdx.x * blockDim.x + threadIdx.x;
    if (n >= NV) return;
    const float4* Y4 = (const float4*)g_Y;
    const float4* in;  int si;
    const float4* add; int sa;
    float4* out;
    if (step == 1)      { in = Y4 + 3; si = 4; add = Y4 + 2; sa = 4; out = (float4*)g_t1; }
    else if (step == 2) { in = (const float4*)g_t1; si = 1; add = Y4 + 1; sa = 4; out = (float4*)g_t2; }
    else                { in = (const float4*)g_t2; si = 1; add = Y4;     sa = 4; out = dout; }
    float4 acc = add[(size_t)n * sa];
    if (step == 3) {
        float4 bv = *(const float4*)b3;
        acc.x += bv.x; acc.y += bv.y; acc.z += bv.z; acc.w += bv.w;
    }
    int beg = g_rowptr[n], end = g_rowptr[n + 1];
    for (int e = beg; e < end; e++) {
        int2 ed = g_edge[e];
        int s = ed.x; float w = __int_as_float(ed.y);
        float4 v = in[(size_t)s * si];
        acc.x = fmaf(w, v.x, acc.x); acc.y = fmaf(w, v.y, acc.y);
        acc.z = fmaf(w, v.z, acc.z); acc.w = fmaf(w, v.w, acc.w);
    }
    out[(size_t)n] = acc;
}

// ------------------------------- HMMA GEMM ---------------------------------
// C(NV,128) = A(NV,K fp16) @ g_Wh(K,128 fp16) + bias, optional ReLU.
// 2-stage cp.async double-buffered pipeline (offsets match R2 layout).
// Block: 256 thr = 8 warps (4x2), BM=128, BN=128, BK=32.
__global__ void __launch_bounds__(256) gemm_tc(int aSel, int lda, int K,
                                               int cSel,
                                               const float* __restrict__ bias,
                                               int relu) {
    __shared__ __half As[2][128 * 40];
    __shared__ __half Bs[2][32 * 136];
    const __half* A = (aSel == 0) ? g_H16 : (aSel == 1) ? g_Ha : g_Hb;
    __half* C = cSel ? g_Hb : g_Ha;

    int tid = threadIdx.x;
    int lane = tid & 31, wid = tid >> 5;
    int warp_m = wid & 3;        // 0..3  -> 32 rows each
    int warp_n = wid >> 2;       // 0..1  -> 64 cols each
    int bm = blockIdx.x * 128;

    float acc[2][8][4];
#pragma unroll
    for (int i = 0; i < 2; i++)
#pragma unroll
        for (int j = 0; j < 8; j++)
#pragma unroll
            for (int l = 0; l < 4; l++) acc[i][j][l] = 0.f;

    int arow = tid >> 1;             // 0..127
    int acol = (tid & 1) * 16;       // 0 or 16 (halves)
    int brow = tid >> 3;             // 0..31
    int bcol = (tid & 7) * 16;       // halves
    int aok  = (bm + arow < NV) ? 16 : 0;
    const __half* aptr = A + (size_t)((bm + arow < NV) ? bm + arow : NV - 1) * lda;
    // dst second fragment = +8 halves = +16 BYTES
    unsigned adst0 = (unsigned)__cvta_generic_to_shared(&As[0][arow * 40 + acol]);
    unsigned adst1 = (unsigned)__cvta_generic_to_shared(&As[1][arow * 40 + acol]);
    unsigned bdst0 = (unsigned)__cvta_generic_to_shared(&Bs[0][brow * 136 + bcol]);
    unsigned bdst1 = (unsigned)__cvta_generic_to_shared(&Bs[1][brow * 136 + bcol]);

    // prologue: load tile 0 into buffer 0
    asm volatile("cp.async.ca.shared.global [%0], [%1], 16, %2;\n"
                 :: "r"(adst0), "l"(aptr + acol), "r"(aok));
    asm volatile("cp.async.ca.shared.global [%0], [%1], 16, %2;\n"
                 :: "r"(adst0 + 16), "l"(aptr + acol + 8), "r"(aok));
    asm volatile("cp.async.ca.shared.global [%0], [%1], 16;\n"
                 :: "r"(bdst0), "l"(g_Wh + (size_t)brow * 128 + bcol));
    asm volatile("cp.async.ca.shared.global [%0], [%1], 16;\n"
                 :: "r"(bdst0 + 16), "l"(g_Wh + (size_t)brow * 128 + bcol + 8));
    asm volatile("cp.async.commit_group;\n" ::: "memory");

    int niter = K >> 5;
    for (int it = 0; it < niter; it++) {
        int b = it & 1;
        if (it + 1 < niter) {
            int kt = (it + 1) << 5;
            unsigned ad = b ? adst0 : adst1;
            unsigned bd = b ? bdst0 : bdst1;
            asm volatile("cp.async.ca.shared.global [%0], [%1], 16, %2;\n"
                         :: "r"(ad), "l"(aptr + kt + acol), "r"(aok));
            asm volatile("cp.async.ca.shared.global [%0], [%1], 16, %2;\n"
                         :: "r"(ad + 16), "l"(aptr + kt + acol + 8), "r"(aok));
            asm volatile("cp.async.ca.shared.global [%0], [%1], 16;\n"
                         :: "r"(bd), "l"(g_Wh + (size_t)(kt + brow) * 128 + bcol));
            asm volatile("cp.async.ca.shared.global [%0], [%1], 16;\n"
                         :: "r"(bd + 16), "l"(g_Wh + (size_t)(kt + brow) * 128 + bcol + 8));
            asm volatile("cp.async.commit_group;\n" ::: "memory");
            asm volatile("cp.async.wait_group 1;\n" ::: "memory");
        } else {
            asm volatile("cp.async.wait_group 0;\n" ::: "memory");
        }
        __syncthreads();

#pragma unroll
        for (int ks = 0; ks < 2; ks++) {
            int k0 = ks * 16;
            unsigned af[2][4];
#pragma unroll
            for (int tm = 0; tm < 2; tm++) {
                int row = warp_m * 32 + tm * 16 + (lane & 15);
                int col = k0 + (lane >> 4) * 8;
                unsigned addr = (unsigned)__cvta_generic_to_shared(&As[b][row * 40 + col]);
                asm volatile(
                    "ldmatrix.sync.aligned.m8n8.x4.shared.b16 {%0,%1,%2,%3}, [%4];"
                    : "=r"(af[tm][0]), "=r"(af[tm][1]), "=r"(af[tm][2]), "=r"(af[tm][3])
                    : "r"(addr));
            }
            unsigned bf[8][2];
#pragma unroll
            for (int tp = 0; tp < 4; tp++) {
                int row = k0 + (lane & 15);
                int col = warp_n * 64 + tp * 16 + (lane >> 4) * 8;
                unsigned addr = (unsigned)__cvta_generic_to_shared(&Bs[b][row * 136 + col]);
                unsigned r0, r1, r2, r3;
                asm volatile(
                    "ldmatrix.sync.aligned.m8n8.x4.trans.shared.b16 {%0,%1,%2,%3}, [%4];"
                    : "=r"(r0), "=r"(r1), "=r"(r2), "=r"(r3)
                    : "r"(addr));
                bf[tp * 2][0] = r0; bf[tp * 2][1] = r1;
                bf[tp * 2 + 1][0] = r2; bf[tp * 2 + 1][1] = r3;
            }
#pragma unroll
            for (int tm = 0; tm < 2; tm++)
#pragma unroll
                for (int tn = 0; tn < 8; tn++) {
                    asm volatile(
                        "mma.sync.aligned.m16n8k16.row.col.f32.f16.f16.f32 "
                        "{%0,%1,%2,%3}, {%4,%5,%6,%7}, {%8,%9}, {%0,%1,%2,%3};"
                        : "+f"(acc[tm][tn][0]), "+f"(acc[tm][tn][1]),
                          "+f"(acc[tm][tn][2]), "+f"(acc[tm][tn][3])
                        : "r"(af[tm][0]), "r"(af[tm][1]), "r"(af[tm][2]), "r"(af[tm][3]),
                          "r"(bf[tn][0]), "r"(bf[tn][1]));
                }
        }
        __syncthreads();
    }

#pragma unroll
    for (int tm = 0; tm < 2; tm++) {
        int rbase = bm + warp_m * 32 + tm * 16 + (lane >> 2);
#pragma unroll
        for (int tn = 0; tn < 8; tn++) {
            int cc = warp_n * 64 + tn * 8 + (lane & 3) * 2;
            float bv0 = __ldg(bias + cc), bv1 = __ldg(bias + cc + 1);
            if (rbase < NV) {
                float v0 = acc[tm][tn][0] + bv0;
                float v1 = acc[tm][tn][1] + bv1;
                if (relu) { v0 = fmaxf(v0, 0.f); v1 = fmaxf(v1, 0.f); }
                *(__half2*)(C + (size_t)rbase * 512 + cc) = __floats2half2_rn(v0, v1);
            }
            if (rbase + 8 < NV) {
                float v2 = acc[tm][tn][2] + bv0;
                float v3 = acc[tm][tn][3] + bv1;
                if (relu) { v2 = fmaxf(v2, 0.f); v3 = fmaxf(v3, 0.f); }
                *(__half2*)(C + (size_t)(rbase + 8) * 512 + cc) = __floats2half2_rn(v2, v3);
            }
        }
    }
}

// Layer-3 GEMM: Y(NV,16 fp32) = h(NV,128 fp16 in g_Ha chunk0, lda=512) @ W3cat
// with W3cat column (k*4+j) = W3[k][:,j]  (W3 fp32, kept fp32 in smem).
__global__ void __launch_bounds__(256) gemm16h(const float* __restrict__ W3) {
    __shared__ float Bs[128 * 16];
    int tid = threadIdx.x;
    for (int idx = tid; idx < 2048; idx += 256) {
        int k = idx >> 9, rem = idx & 511, i2 = rem >> 2, j = rem & 3;
        Bs[i2 * 16 + (k << 2) + j] = W3[idx];
    }
    __syncthreads();
    int g = tid >> 4, n = tid & 15;
    int m = blockIdx.x * 16 + g;
    if (m >= NV) return;
    const __half* a = g_Ha + (size_t)m * 512;
    float acc = 0.f;
#pragma unroll 8
    for (int k = 0; k < 128; k++)
        acc = fmaf(__half2float(a[k]), Bs[k * 16 + n], acc);
    g_Y[(size_t)m * 16 + n] = acc;
}

// ------------------------------- driver ------------------------------------
extern "C" void kernel_launch(void* const* d_in, const int* in_sizes, int n_in,
                              void* d_out, int out_size) {
    const float* x  = (const float*)d_in[0];
    const void*  ei = d_in[1];
    const float* ew = (const float*)d_in[2];
    const float* W0 = (const float*)d_in[3];
    const float* b0 = (const float*)d_in[4];
    const float* W1 = (const float*)d_in[5];
    const float* b1 = (const float*)d_in[6];
    const float* W2 = (const float*)d_in[7];
    const float* b2 = (const float*)d_in[8];
    const float* W3 = (const float*)d_in[9];
    const float* b3 = (const float*)d_in[10];

    const int* ei32 = (const int*)ei;
    const long long* ei64 = (const long long*)ei;

    k_init<<<(NV + 255) / 256, 256>>>();
    k_detect<<<1, 1024>>>(ei32);
    k_degcnt<<<(NE + 255) / 256, 256>>>(ei32, ei64, ew);
    k_rsqrt<<<(NV + 255) / 256, 256>>>();
    k_scan1<<<NB_SCAN, 1024>>>();
    k_scan2<<<1, 128>>>();
    k_scan3<<<(NV + 256) / 256, 256>>>();
    k_scatter<<<(NE + 255) / 256, 256>>>(ei32, ei64, ew);
    k_copyx<<<(NV * 4 + 255) / 256, 256>>>(x);

    const int GEMM_BLOCKS = (NV + 127) / 128;

    // layer 0: propagate width 16, GEMM (NV,64)@(64,128) -> Ha chunk0, ReLU
    for (int k = 1; k <= 3; k++)
        spmm16h<<<(NV * 2 + 255) / 256, 256>>>(k);
    k_cvtW<<<(64 * 128 + 255) / 256, 256>>>(W0, 64 * 128);
    gemm_tc<<<GEMM_BLOCKS, 256>>>(0, 64, 64, 0, b0, 1);

    // layer 1: propagate width 128 in Ha, GEMM (NV,512)@(512,128) -> Hb, ReLU
    for (int k = 1; k <= 3; k++)
        spmm128h<<<(NV * 32 + 255) / 256, 256>>>(0, k);
    k_cvtW<<<(512 * 128 + 255) / 256, 256>>>(W1, 512 * 128);
    gemm_tc<<<GEMM_BLOCKS, 256>>>(1, 512, 512, 1, b1, 1);

    // layer 2: propagate width 128 in Hb, GEMM -> Ha chunk0, ReLU
    for (int k = 1; k <= 3; k++)
        spmm128h<<<(NV * 32 + 255) / 256, 256>>>(1, k);
    k_cvtW<<<(512 * 128 + 255) / 256, 256>>>(W2, 512 * 128);
    gemm_tc<<<GEMM_BLOCKS, 256>>>(2, 512, 512, 0, b2, 1);

    // layer 3: y_k = h @ W3[k]; Horner with width-4 fp32 SpMMs
    gemm16h<<<(NV + 15) / 16, 256>>>(W3);
    spmm4<<<(NV + 255) / 256, 256>>>(1, nullptr, nullptr);
    spmm4<<<(NV + 255) / 256, 256>>>(2, nullptr, nullptr);
    spmm4<<<(NV + 255) / 256, 256>>>(3, b3, (float4*)d_out);
}